// round 16
// baseline (speedup 1.0000x reference)
#include <cuda_runtime.h>

// RelationAwareAttention: B=1, H=8, L=512, D=64
// out = concat(attn_sum[1,8,512,64], p_attn[1,8,512,512]) as float32.
//
// A: S1 = Q K^T per head — FFMA2 (fma.rn.f32x2) tiled GEMM, 512 CTAs.
//    Triggers programmatic launch completion at entry.
// B: launched with PDL (programmatic stream serialization). Phase 1 streams
//    rk and computes raw dots WITHOUT s1; cudaGridDependencySynchronize()
//    then gates the s1 add + softmax. A (~10us) hides under phase 1 (~70us).

#define L_SEQ 512
#define D_DIM 64
#define H_HEADS 8

__device__ float g_s1[(size_t)H_HEADS * L_SEQ * L_SEQ];   // 8.4 MB scratch

__device__ __forceinline__ unsigned long long pack2(float lo, float hi) {
    unsigned long long r;
    asm("mov.b64 %0, {%1, %2};" : "=l"(r) : "f"(lo), "f"(hi));
    return r;
}
__device__ __forceinline__ void unpack2(unsigned long long p, float& lo, float& hi) {
    asm("mov.b64 {%0, %1}, %2;" : "=f"(lo), "=f"(hi) : "l"(p));
}
__device__ __forceinline__ void fma2(unsigned long long& d,
                                     unsigned long long a, unsigned long long b) {
    asm("fma.rn.f32x2 %0, %1, %2, %0;" : "+l"(d) : "l"(a), "l"(b));
}

// ---------------- Kernel A: S1 = Q K^T (FFMA2) ----------------
__global__ __launch_bounds__(256)
void qk_kernel(const float* __restrict__ q, const float* __restrict__ k)
{
    // Allow the dependent kernel to start launching right away; its
    // cudaGridDependencySynchronize() still waits for our true completion.
    cudaTriggerProgrammaticLaunchCompletion();

    const int jt = blockIdx.x;            // 8
    const int it = blockIdx.y;            // 8
    const int h  = blockIdx.z;            // 8
    const int i0 = it << 6, j0 = jt << 6;
    __shared__ float sqT[64][68];         // [kk][i-local], float4 reads 16B-aligned
    __shared__ float skT[64][68];         // [kk][j-local]
    const int tid = threadIdx.x;

    for (int idx = tid; idx < 64 * 16; idx += 256) {
        const int row = idx >> 4, c4 = (idx & 15) << 2;
        const float4 a = *reinterpret_cast<const float4*>(
            q + ((size_t)h * L_SEQ + i0 + row) * D_DIM + c4);
        sqT[c4 + 0][row] = a.x; sqT[c4 + 1][row] = a.y;
        sqT[c4 + 2][row] = a.z; sqT[c4 + 3][row] = a.w;
        const float4 b = *reinterpret_cast<const float4*>(
            k + ((size_t)h * L_SEQ + j0 + row) * D_DIM + c4);
        skT[c4 + 0][row] = b.x; skT[c4 + 1][row] = b.y;
        skT[c4 + 2][row] = b.z; skT[c4 + 3][row] = b.w;
    }
    __syncthreads();

    const int ty = tid >> 4, tx = tid & 15;   // 16 x 16 threads, 4x4 outputs each
    unsigned long long acc01[4] = {0ull, 0ull, 0ull, 0ull};
    unsigned long long acc23[4] = {0ull, 0ull, 0ull, 0ull};

    #pragma unroll 8
    for (int kk = 0; kk < 64; ++kk) {
        const float4 av = *reinterpret_cast<const float4*>(&sqT[kk][4 * ty]);
        const float4 bv = *reinterpret_cast<const float4*>(&skT[kk][4 * tx]);
        const unsigned long long b01 = pack2(bv.x, bv.y);
        const unsigned long long b23 = pack2(bv.z, bv.w);
        const unsigned long long a0 = pack2(av.x, av.x);
        const unsigned long long a1 = pack2(av.y, av.y);
        const unsigned long long a2 = pack2(av.z, av.z);
        const unsigned long long a3 = pack2(av.w, av.w);
        fma2(acc01[0], a0, b01); fma2(acc23[0], a0, b23);
        fma2(acc01[1], a1, b01); fma2(acc23[1], a1, b23);
        fma2(acc01[2], a2, b01); fma2(acc23[2], a2, b23);
        fma2(acc01[3], a3, b01); fma2(acc23[3], a3, b23);
    }

    #pragma unroll
    for (int r = 0; r < 4; ++r) {
        float4 o;
        unpack2(acc01[r], o.x, o.y);
        unpack2(acc23[r], o.z, o.w);
        *reinterpret_cast<float4*>(
            g_s1 + ((size_t)h * L_SEQ + i0 + 4 * ty + r) * L_SEQ + j0 + 4 * tx) = o;
    }
}

// ---------------- Kernel B: relation stream + softmax + fused PV ----------------
__global__ __launch_bounds__(256)
void rel_attn_kernel(const float* __restrict__ q_g,
                     const float* __restrict__ v_g,
                     const float* __restrict__ rk_g,
                     const float* __restrict__ rv_g,
                     const int*   __restrict__ mask_g,
                     float* __restrict__ out_attn,
                     float* __restrict__ out_p)
{
    const int i    = blockIdx.x;
    const int h    = blockIdx.y;
    const int tid  = threadIdx.x;
    const int warp = tid >> 5;
    const int lane = tid & 31;
    const int half = lane >> 4;
    const int hl   = lane & 15;

    __shared__ float  s_score[L_SEQ];
    __shared__ int    s_mask[L_SEQ];
    __shared__ float  s_red[8];
    __shared__ float4 s_acc[16][16];

    const float* q     = q_g  + ((size_t)h * L_SEQ + i) * D_DIM;
    const float* rk    = rk_g + (((size_t)h * L_SEQ + i) * L_SEQ) * D_DIM;
    const int*   mrow  = mask_g + (size_t)i * L_SEQ;          // broadcast over h (B=1)
    const float* s1row = g_s1 + ((size_t)h * L_SEQ + i) * L_SEQ;

    // Prologue (independent of kernel A): mask row into smem.
    s_mask[tid]       = mrow[tid];
    s_mask[tid + 256] = mrow[tid + 256];

    // Phase 1: raw dot p[j] = q . rk[i,j]  (no s1 yet — overlaps kernel A).
    const float4 q4 = *reinterpret_cast<const float4*>(q + 4 * hl);

    #pragma unroll 8
    for (int jj = 0; jj < 32; ++jj) {
        const int j = (warp << 6) + (jj << 1) + half;
        const float4 rr = __ldcs(reinterpret_cast<const float4*>(rk + (size_t)j * D_DIM + 4 * hl));
        float p = q4.x * rr.x + q4.y * rr.y + q4.z * rr.z + q4.w * rr.w;
        p += __shfl_xor_sync(0xffffffffu, p, 8);
        p += __shfl_xor_sync(0xffffffffu, p, 4);
        p += __shfl_xor_sync(0xffffffffu, p, 2);
        p += __shfl_xor_sync(0xffffffffu, p, 1);
        if (hl == 0) s_score[j] = p;
    }
    __syncthreads();

    // Wait for kernel A's S1 to be globally visible, then finish the scores.
    cudaGridDependencySynchronize();

    float v0 = (s_score[tid]       + s1row[tid])       * 0.125f;   // 1/sqrt(64)
    float v1 = (s_score[tid + 256] + s1row[tid + 256]) * 0.125f;
    if (s_mask[tid] == 0)       v0 = -1e9f;
    if (s_mask[tid + 256] == 0) v1 = -1e9f;

    // Phase 2: softmax over j (thread owns tid, tid+256).
    float m = fmaxf(v0, v1);
    #pragma unroll
    for (int o = 16; o > 0; o >>= 1)
        m = fmaxf(m, __shfl_xor_sync(0xffffffffu, m, o));
    if (lane == 0) s_red[warp] = m;
    __syncthreads();
    if (tid == 0) {
        float mm = s_red[0];
        #pragma unroll
        for (int w = 1; w < 8; ++w) mm = fmaxf(mm, s_red[w]);
        s_red[0] = mm;
    }
    __syncthreads();
    m = s_red[0];
    __syncthreads();

    const float e0 = __expf(v0 - m);
    const float e1 = __expf(v1 - m);
    float ssum = e0 + e1;
    #pragma unroll
    for (int o = 16; o > 0; o >>= 1)
        ssum += __shfl_xor_sync(0xffffffffu, ssum, o);
    if (lane == 0) s_red[warp] = ssum;
    __syncthreads();
    if (tid == 0) {
        float tot = s_red[0];
        #pragma unroll
        for (int w = 1; w < 8; ++w) tot += s_red[w];
        s_red[0] = tot;
    }
    __syncthreads();
    const float inv = 1.0f / s_red[0];

    const float p0 = e0 * inv;
    const float p1 = e1 * inv;
    s_score[tid]       = p0;
    s_score[tid + 256] = p1;

    // p_attn written once, never re-read: streaming stores keep L2 for v/s1.
    const size_t pbase = ((size_t)h * L_SEQ + i) * L_SEQ;
    __stcs(&out_p[pbase + tid], p0);
    __stcs(&out_p[pbase + tid + 256], p1);
    __syncthreads();

    // Phase 3: out_i[d] = sum_j p[j] * (v[j,d] + rv[i,j,d]).
    const int gid = (warp << 1) + half;
    const float* vrow = v_g  + (size_t)h * L_SEQ * D_DIM;
    const float* rv   = rv_g + (((size_t)h * L_SEQ + i) * L_SEQ) * D_DIM;

    float4 acc = make_float4(0.f, 0.f, 0.f, 0.f);
    #pragma unroll 4
    for (int j = gid; j < L_SEQ; j += 16) {
        const float  pj  = s_score[j];
        const size_t off = (size_t)j * D_DIM + 4 * hl;
        const float4 vv  = *reinterpret_cast<const float4*>(vrow + off);
        const float4 rr  = __ldcs(reinterpret_cast<const float4*>(rv + off));
        acc.x += pj * (vv.x + rr.x);
        acc.y += pj * (vv.y + rr.y);
        acc.z += pj * (vv.z + rr.z);
        acc.w += pj * (vv.w + rr.w);
    }
    s_acc[gid][hl] = acc;
    __syncthreads();

    if (tid < 16) {
        float4 r = make_float4(0.f, 0.f, 0.f, 0.f);
        #pragma unroll
        for (int gg = 0; gg < 16; ++gg) {
            const float4 a = s_acc[gg][tid];
            r.x += a.x; r.y += a.y; r.z += a.z; r.w += a.w;
        }
        float4* oa = reinterpret_cast<float4*>(out_attn + ((size_t)h * L_SEQ + i) * D_DIM);
        oa[tid] = r;
    }
}

extern "C" void kernel_launch(void* const* d_in, const int* in_sizes, int n_in,
                              void* d_out, int out_size)
{
    const float* q    = (const float*)d_in[0];
    const float* k    = (const float*)d_in[1];
    const float* v    = (const float*)d_in[2];
    const float* rk   = (const float*)d_in[3];
    const float* rv   = (const float*)d_in[4];
    const int*   mask = (const int*)  d_in[5];

    float* out      = (float*)d_out;
    float* out_attn = out;                                        // [1,8,512,64]
    float* out_p    = out + (size_t)H_HEADS * L_SEQ * D_DIM;      // [1,8,512,512]

    qk_kernel<<<dim3(8, 8, 8), 256>>>(q, k);

    // Launch B with programmatic dependent launch: it starts streaming rk
    // while A finishes; cudaGridDependencySynchronize() in B gates the s1 use.
    cudaLaunchConfig_t cfg = {};
    cfg.gridDim  = dim3(L_SEQ, H_HEADS);
    cfg.blockDim = dim3(256);
    cfg.stream   = 0;
    cudaLaunchAttribute attrs[1];
    attrs[0].id = cudaLaunchAttributeProgrammaticStreamSerialization;
    attrs[0].val.programmaticStreamSerializationAllowed = 1;
    cfg.attrs    = attrs;
    cfg.numAttrs = 1;
    cudaLaunchKernelEx(&cfg, rel_attn_kernel, q, v, rk, rv, mask, out_attn, out_p);
}